// round 12
// baseline (speedup 1.0000x reference)
#include <cuda_runtime.h>
#include <cuda_bf16.h>
#include <cstdint>

// TransposeTDLayer via tf32 mma.sync + cp.async, K=16-chunk double buffer,
// 128-thread CTAs with [64 x 64] tiles, 8 CTAs/SM.
// y[b,p,o] = bias[p,o] + sum_{(k,l):k+2l=p} sum_ci W[k,l,o,ci] * x[b,l,ci]
// Grid 2060: blockIdx = 2*p + mhalf; CTA computes D[64 cout x 64 batch].
// SMEM raw fp32; ldmatrix.b16 yields tf32 fragment layout; tf32 rounding via
// integer +0x1000 (bit-exact vs cvt.rna.tf32, validated round 10).

#define BATCH 64
#define LIN   512
#define CIN   128
#define COUT  128
#define OUTP  1030

// chunk row stride: 16 fp32 + 4 pad = 20 words = 80 B
// (20*r mod 32 = 0,20,8,28,16,4,24,12 -> perfect LDSM bank partition)
#define RSTRIDE 80
#define A_OFF   0
#define A_BYTES (64 * RSTRIDE)             // 5120
#define B_OFF   A_BYTES
#define B_BYTES (64 * RSTRIDE)             // 5120
#define BUF_BYTES (A_BYTES + B_BYTES)      // 10240
#define SMEM_TOTAL (2 * BUF_BYTES)         // 20480/CTA -> 8 CTAs = 163840 B

static __device__ __forceinline__ uint32_t smem_u32(const void* p) {
    uint32_t a;
    asm("{ .reg .u64 t; cvta.to.shared.u64 t, %1; cvt.u32.u64 %0, t; }"
        : "=r"(a) : "l"(p));
    return a;
}

static __device__ __forceinline__ void mma_tf32(
    float* c, const uint32_t* a, const uint32_t* b)
{
    asm volatile(
        "mma.sync.aligned.m16n8k8.row.col.f32.tf32.tf32.f32 "
        "{%0,%1,%2,%3}, {%4,%5,%6,%7}, {%8,%9}, {%0,%1,%2,%3};"
        : "+f"(c[0]), "+f"(c[1]), "+f"(c[2]), "+f"(c[3])
        : "r"(a[0]), "r"(a[1]), "r"(a[2]), "r"(a[3]), "r"(b[0]), "r"(b[1]));
}

static __device__ __forceinline__ void ldsm_x4(uint32_t* r, uint32_t addr) {
    asm volatile("ldmatrix.sync.aligned.m8n8.x4.shared.b16 {%0,%1,%2,%3}, [%4];"
                 : "=r"(r[0]), "=r"(r[1]), "=r"(r[2]), "=r"(r[3]) : "r"(addr));
}

// tf32 round-to-nearest via +half-ulp; tensor core truncates low 13 bits.
static __device__ __forceinline__ uint32_t round_tf32(uint32_t v) {
    return v + 0x1000u;
}

static __device__ __forceinline__ void cpasync16(uint32_t dst, const void* src) {
    asm volatile("cp.async.cg.shared.global [%0], [%1], 16;"
                 :: "r"(dst), "l"(src) : "memory");
}
#define CP_COMMIT() asm volatile("cp.async.commit_group;" ::: "memory")
#define CP_WAIT1()  asm volatile("cp.async.wait_group 1;" ::: "memory")

__global__ void __launch_bounds__(128, 8)
tdconv_tf32h_kernel(const float* __restrict__ x,
                    const float* __restrict__ w,
                    const float* __restrict__ bias,
                    float* __restrict__ y)
{
    extern __shared__ char smem[];
    const uint32_t sbase = smem_u32(smem);

    const int tid  = threadIdx.x;
    const int wid  = tid >> 5;          // 0..3
    const int lane = tid & 31;

    const int p  = blockIdx.x >> 1;     // output position
    const int mh = (blockIdx.x & 1) * 64;   // cout half base (0 or 64)

    const int mrow = (wid >> 1) * 32;   // cout base within half (0,32)
    const int ncol = (wid & 1) * 32;    // batch base (0,32)

    // contributing blocks: k = par + 2j, l = m - j, j in [j0, j1]
    const int par = p & 1;
    const int m   = (p - par) >> 1;
    int j0 = m - (LIN - 1); if (j0 < 0) j0 = 0;
    int j1 = m < 3 ? m : 3;
    const int nblk    = j1 - j0 + 1;
    const int nchunks = 8 * nblk;       // K=16 slices

    // hoisted per-thread cp.async decomposition: rows 0..31 (+32*it), 4 segs
    const int a_row = tid >> 2;                 // 0..31
    const int a_seg = (tid & 3) * 4;            // fp32 offset of 16B segment
    const uint32_t a_soff = (uint32_t)a_row * RSTRIDE + (uint32_t)(tid & 3) * 16;

    // issue cp.async for chunk c (block c>>3, K-slice c&7) into buf[c&1]
    auto issue_chunk = [&](int c) {
        if (c < nchunks) {
            const int j = j0 + (c >> 3);
            const int l = m - j;
            const int k = par + 2 * j;
            const int kh = (c & 7) * 16;
            const float* __restrict__ wp =
                w + (size_t)(k * LIN + l) * (COUT * CIN)
                  + (size_t)(mh + a_row) * CIN + kh + a_seg;
            const float* __restrict__ xp =
                x + ((size_t)a_row * LIN + l) * CIN + kh + a_seg;
            const uint32_t buf = sbase + (uint32_t)(c & 1) * BUF_BYTES;
            #pragma unroll
            for (int it = 0; it < 2; it++)
                cpasync16(buf + A_OFF + a_soff + (uint32_t)it * (32 * RSTRIDE),
                          wp + (size_t)it * (32 * CIN));
            #pragma unroll
            for (int it = 0; it < 2; it++)
                cpasync16(buf + B_OFF + a_soff + (uint32_t)it * (32 * RSTRIDE),
                          xp + (size_t)it * (32 * LIN * CIN));
        }
        CP_COMMIT();   // uniform group counting
    };

    // ldmatrix lane byte-offsets (within chunk)
    const uint32_t a_loff = A_OFF
        + (uint32_t)(mrow + (lane & 7) + ((lane >> 3) & 1) * 8) * RSTRIDE
        + (uint32_t)(lane >> 4) * 16;
    const uint32_t b_loff = B_OFF
        + (uint32_t)(ncol + (lane & 7) + (lane >> 4) * 8) * RSTRIDE
        + (uint32_t)((lane >> 3) & 1) * 16;

    // accumulators init with bias (same across batch cols)
    const int g = lane >> 2;
    float acc[2][4][4];
    #pragma unroll
    for (int mi = 0; mi < 2; mi++) {
        const float b_g  = bias[p * COUT + mh + mrow + mi * 16 + g];
        const float b_g8 = bias[p * COUT + mh + mrow + mi * 16 + g + 8];
        #pragma unroll
        for (int ni = 0; ni < 4; ni++) {
            acc[mi][ni][0] = b_g;  acc[mi][ni][1] = b_g;
            acc[mi][ni][2] = b_g8; acc[mi][ni][3] = b_g8;
        }
    }

    issue_chunk(0);
    issue_chunk(1);

    for (int c = 0; c < nchunks; c++) {
        CP_WAIT1();
        __syncthreads();

        const uint32_t buf = sbase + (uint32_t)(c & 1) * BUF_BYTES;
        const uint32_t ab = buf + a_loff;
        const uint32_t bb = buf + b_loff;

        #pragma unroll
        for (int ks = 0; ks < 2; ks++) {           // 2 k8-steps over K=16
            const uint32_t koff = (uint32_t)ks * 32;
            uint32_t a[2][4], b[2][4];
            #pragma unroll
            for (int mi = 0; mi < 2; mi++)
                ldsm_x4(a[mi], ab + (uint32_t)mi * (16 * RSTRIDE) + koff);
            #pragma unroll
            for (int pr = 0; pr < 2; pr++)
                ldsm_x4(b[pr], bb + (uint32_t)pr * (16 * RSTRIDE) + koff);

            #pragma unroll
            for (int mi = 0; mi < 2; mi++)
                #pragma unroll
                for (int q = 0; q < 4; q++) a[mi][q] = round_tf32(a[mi][q]);
            #pragma unroll
            for (int pr = 0; pr < 2; pr++)
                #pragma unroll
                for (int q = 0; q < 4; q++) b[pr][q] = round_tf32(b[pr][q]);

            #pragma unroll
            for (int mi = 0; mi < 2; mi++)
                #pragma unroll
                for (int ni = 0; ni < 4; ni++)
                    mma_tf32(acc[mi][ni], a[mi], &b[ni >> 1][(ni & 1) * 2]);
        }

        __syncthreads();          // all warps done reading buf[c&1]
        issue_chunk(c + 2);       // refill (commits even when exhausted)
    }

    // ---- epilogue: D[o,b] -> y[b,p,o] ----
    const int t = lane & 3;
    #pragma unroll
    for (int mi = 0; mi < 2; mi++) {
        const int o0 = mh + mrow + mi * 16 + g;
        const int o8 = o0 + 8;
        #pragma unroll
        for (int ni = 0; ni < 4; ni++) {
            const int b0 = ncol + ni * 8 + 2 * t;
            float* y0 = y + ((size_t)b0 * OUTP + p) * COUT;
            float* y1 = y0 + (size_t)OUTP * COUT;
            y0[o0] = acc[mi][ni][0];
            y1[o0] = acc[mi][ni][1];
            y0[o8] = acc[mi][ni][2];
            y1[o8] = acc[mi][ni][3];
        }
    }
}

extern "C" void kernel_launch(void* const* d_in, const int* in_sizes, int n_in,
                              void* d_out, int out_size)
{
    const float* x    = (const float*)d_in[0];  // (64,512,128)
    const float* w    = (const float*)d_in[1];  // (8,512,128,128)
    const float* bias = (const float*)d_in[2];  // (1030,128)
    float* y = (float*)d_out;                   // (64,1030,128)

    tdconv_tf32h_kernel<<<2 * OUTP, 128, SMEM_TOTAL>>>(x, w, bias, y);
}

// round 13
// speedup vs baseline: 1.1756x; 1.1756x over previous
#include <cuda_runtime.h>
#include <cuda_bf16.h>
#include <cstdint>

// TransposeTDLayer via tf32 mma.sync + cp.async, K=16-stage TRIPLE buffer,
// 4 CTAs/SM, one __syncthreads per stage, 2 load-stages always in flight.
// y[b,p,o] = bias[p,o] + sum_{(k,l):k+2l=p} sum_ci W[k,l,o,ci] * x[b,l,ci]
// Per p: D[128 x 64] = sum_j A_j[128x128] B_j[64x128]^T, K-major fp32.
// SMEM raw fp32; ldmatrix.b16 yields tf32 fragment layout; tf32 rounding via
// integer +0x1000 (bit-exact vs cvt.rna.tf32, validated round 10).

#define BATCH 64
#define LIN   512
#define CIN   128
#define COUT  128
#define OUTP  1030

// stage row stride: 16 fp32 + 4 pad = 20 words = 80 B
// (20*r mod 32 = 0,20,8,28,16,4,24,12 -> conflict-free LDSM partition)
#define RSTRIDE 80
#define A_OFF   0
#define A_BYTES (128 * RSTRIDE)            // 10240
#define B_OFF   A_BYTES
#define B_BYTES (64 * RSTRIDE)             // 5120
#define BUF_BYTES (A_BYTES + B_BYTES)      // 15360
#define NSTAGE  3
#define SMEM_TOTAL (NSTAGE * BUF_BYTES)    // 46080/CTA -> 4 CTAs = 184320 B

static __device__ __forceinline__ uint32_t smem_u32(const void* p) {
    uint32_t a;
    asm("{ .reg .u64 t; cvta.to.shared.u64 t, %1; cvt.u32.u64 %0, t; }"
        : "=r"(a) : "l"(p));
    return a;
}

static __device__ __forceinline__ void mma_tf32(
    float* c, const uint32_t* a, const uint32_t* b)
{
    asm volatile(
        "mma.sync.aligned.m16n8k8.row.col.f32.tf32.tf32.f32 "
        "{%0,%1,%2,%3}, {%4,%5,%6,%7}, {%8,%9}, {%0,%1,%2,%3};"
        : "+f"(c[0]), "+f"(c[1]), "+f"(c[2]), "+f"(c[3])
        : "r"(a[0]), "r"(a[1]), "r"(a[2]), "r"(a[3]), "r"(b[0]), "r"(b[1]));
}

static __device__ __forceinline__ void ldsm_x4(uint32_t* r, uint32_t addr) {
    asm volatile("ldmatrix.sync.aligned.m8n8.x4.shared.b16 {%0,%1,%2,%3}, [%4];"
                 : "=r"(r[0]), "=r"(r[1]), "=r"(r[2]), "=r"(r[3]) : "r"(addr));
}

// tf32 round-to-nearest via +half-ulp; tensor core truncates low 13 bits.
static __device__ __forceinline__ uint32_t round_tf32(uint32_t v) {
    return v + 0x1000u;
}

static __device__ __forceinline__ void cpasync16(uint32_t dst, const void* src) {
    asm volatile("cp.async.cg.shared.global [%0], [%1], 16;"
                 :: "r"(dst), "l"(src) : "memory");
}
#define CP_COMMIT() asm volatile("cp.async.commit_group;" ::: "memory")
#define CP_WAIT1()  asm volatile("cp.async.wait_group 1;" ::: "memory")

__global__ void __launch_bounds__(256, 4)
tdconv_tf32s3_kernel(const float* __restrict__ x,
                     const float* __restrict__ w,
                     const float* __restrict__ bias,
                     float* __restrict__ y)
{
    extern __shared__ char smem[];
    const uint32_t sbase = smem_u32(smem);

    const int p    = blockIdx.x;
    const int tid  = threadIdx.x;
    const int wid  = tid >> 5;
    const int lane = tid & 31;

    const int mrow = (wid >> 1) * 32;   // cout base (0,32,64,96)
    const int ncol = (wid & 1) * 32;    // batch base (0,32)

    // contributing blocks: k = par + 2j, l = m - j, j in [j0, j1]
    const int par = p & 1;
    const int m   = (p - par) >> 1;
    int j0 = m - (LIN - 1); if (j0 < 0) j0 = 0;
    int j1 = m < 3 ? m : 3;
    const int nblk    = j1 - j0 + 1;
    const int nchunks = 8 * nblk;       // K=16 slices

    // hoisted per-thread cp.async decomposition
    const int a_row = tid >> 2;                 // 0..63
    const int a_seg = (tid & 3) * 4;            // fp32 offset of 16B segment
    const uint32_t a_soff = (uint32_t)a_row * RSTRIDE + (uint32_t)(tid & 3) * 16;

    // issue cp.async for chunk c (block c>>3, K-slice c&7) into stage buffer sb
    auto issue_chunk = [&](int c, uint32_t sb) {
        if (c < nchunks) {
            const int j = j0 + (c >> 3);
            const int l = m - j;
            const int k = par + 2 * j;
            const int kh = (c & 7) * 16;
            const float* __restrict__ wp =
                w + (size_t)(k * LIN + l) * (COUT * CIN)
                  + (size_t)a_row * CIN + kh + a_seg;
            const float* __restrict__ xp =
                x + ((size_t)a_row * LIN + l) * CIN + kh + a_seg;
            const uint32_t buf = sbase + sb * BUF_BYTES;
            // A: 128 rows x 4 seg = 512 tasks; rows a_row + 64*it
            #pragma unroll
            for (int it = 0; it < 2; it++)
                cpasync16(buf + A_OFF + a_soff + (uint32_t)it * (64 * RSTRIDE),
                          wp + (size_t)it * (64 * CIN));
            // B: 64 rows x 4 seg = 256 tasks; one per thread
            cpasync16(buf + B_OFF + a_soff, xp);
        }
        CP_COMMIT();   // uniform group counting
    };

    // ldmatrix lane byte-offsets (within stage)
    const uint32_t a_loff = A_OFF
        + (uint32_t)(mrow + (lane & 7) + ((lane >> 3) & 1) * 8) * RSTRIDE
        + (uint32_t)(lane >> 4) * 16;
    const uint32_t b_loff = B_OFF
        + (uint32_t)(ncol + (lane & 7) + (lane >> 4) * 8) * RSTRIDE
        + (uint32_t)((lane >> 3) & 1) * 16;

    // accumulators init with bias (same across batch cols)
    const int g = lane >> 2;
    float acc[2][4][4];
    #pragma unroll
    for (int mi = 0; mi < 2; mi++) {
        const float b_g  = bias[p * COUT + mrow + mi * 16 + g];
        const float b_g8 = bias[p * COUT + mrow + mi * 16 + g + 8];
        #pragma unroll
        for (int ni = 0; ni < 4; ni++) {
            acc[mi][ni][0] = b_g;  acc[mi][ni][1] = b_g;
            acc[mi][ni][2] = b_g8; acc[mi][ni][3] = b_g8;
        }
    }

    // prologue: 2 stages in flight
    issue_chunk(0, 0);
    issue_chunk(1, 1);

    int bc = 0;        // stage buffer of current chunk
    int bn = 2;        // stage buffer for chunk c+2 (free: readers done last iter)
    for (int c = 0; c < nchunks; c++) {
        CP_WAIT1();               // chunk c landed (c+1 may still be in flight)
        __syncthreads();          // all threads' copies of chunk c visible

        issue_chunk(c + 2, (uint32_t)bn);   // refill before compute

        const uint32_t buf = sbase + (uint32_t)bc * BUF_BYTES;
        const uint32_t ab = buf + a_loff;
        const uint32_t bb = buf + b_loff;

        #pragma unroll
        for (int ks = 0; ks < 2; ks++) {           // 2 k8-steps over K=16
            const uint32_t koff = (uint32_t)ks * 32;
            uint32_t a[2][4], b[2][4];
            #pragma unroll
            for (int mi = 0; mi < 2; mi++)
                ldsm_x4(a[mi], ab + (uint32_t)mi * (16 * RSTRIDE) + koff);
            #pragma unroll
            for (int pr = 0; pr < 2; pr++)
                ldsm_x4(b[pr], bb + (uint32_t)pr * (16 * RSTRIDE) + koff);

            #pragma unroll
            for (int mi = 0; mi < 2; mi++)
                #pragma unroll
                for (int q = 0; q < 4; q++) a[mi][q] = round_tf32(a[mi][q]);
            #pragma unroll
            for (int pr = 0; pr < 2; pr++)
                #pragma unroll
                for (int q = 0; q < 4; q++) b[pr][q] = round_tf32(b[pr][q]);

            #pragma unroll
            for (int mi = 0; mi < 2; mi++)
                #pragma unroll
                for (int ni = 0; ni < 4; ni++)
                    mma_tf32(acc[mi][ni], a[mi], &b[ni >> 1][(ni & 1) * 2]);
        }

        bc = (bc == NSTAGE - 1) ? 0 : bc + 1;
        bn = (bn == NSTAGE - 1) ? 0 : bn + 1;
    }

    // ---- epilogue: D[o,b] -> y[b,p,o] ----
    const int t = lane & 3;
    #pragma unroll
    for (int mi = 0; mi < 2; mi++) {
        const int o0 = mrow + mi * 16 + g;
        const int o8 = o0 + 8;
        #pragma unroll
        for (int ni = 0; ni < 4; ni++) {
            const int b0 = ncol + ni * 8 + 2 * t;
            float* y0 = y + ((size_t)b0 * OUTP + p) * COUT;
            float* y1 = y0 + (size_t)OUTP * COUT;
            y0[o0] = acc[mi][ni][0];
            y1[o0] = acc[mi][ni][1];
            y0[o8] = acc[mi][ni][2];
            y1[o8] = acc[mi][ni][3];
        }
    }
}

extern "C" void kernel_launch(void* const* d_in, const int* in_sizes, int n_in,
                              void* d_out, int out_size)
{
    const float* x    = (const float*)d_in[0];  // (64,512,128)
    const float* w    = (const float*)d_in[1];  // (8,512,128,128)
    const float* bias = (const float*)d_in[2];  // (1030,128)
    float* y = (float*)d_out;                   // (64,1030,128)

    tdconv_tf32s3_kernel<<<OUTP, 256, SMEM_TOTAL>>>(x, w, bias, y);
}

// round 14
// speedup vs baseline: 1.2963x; 1.1027x over previous
#include <cuda_runtime.h>
#include <cstdint>

// TransposeTDLayer via tf32 mma.sync + cp.async, K=16-stage QUAD buffer,
// issue-lead 2, XOR-swizzled packed smem (no padding), 4 CTAs/SM.
// y[b,p,o] = bias[p,o] + sum_{(k,l):k+2l=p} sum_ci W[k,l,o,ci] * x[b,l,ci]
// Per p: D[128 x 64] = sum_j A_j[128x128] B_j[64x128]^T, K-major fp32.
// Swizzle: 64B rows paired into 128B lines; 16B granule g at row r lands at
// line (r>>1), granule ((g + (r&1)*4) ^ ((r>>1)&7)) -> conflict-free LDSM.
// tf32 rounding via +0x1000 (bit-exact vs cvt.rna.tf32, validated round 10).

#define BATCH 64
#define LIN   512
#define CIN   128
#define COUT  128
#define OUTP  1030

#define A_OFF   0
#define A_BYTES 8192                       // 128 rows x 64B packed
#define B_OFF   A_BYTES
#define B_BYTES 4096                       // 64 rows x 64B packed
#define BUF_BYTES (A_BYTES + B_BYTES)      // 12288
#define NSTAGE  4
#define SMEM_TOTAL (NSTAGE * BUF_BYTES)    // 49152/CTA -> 4 CTAs/SM easily

static __device__ __forceinline__ uint32_t smem_u32(const void* p) {
    uint32_t a;
    asm("{ .reg .u64 t; cvta.to.shared.u64 t, %1; cvt.u32.u64 %0, t; }"
        : "=r"(a) : "l"(p));
    return a;
}

static __device__ __forceinline__ void mma_tf32(
    float* c, const uint32_t* a, const uint32_t* b)
{
    asm volatile(
        "mma.sync.aligned.m16n8k8.row.col.f32.tf32.tf32.f32 "
        "{%0,%1,%2,%3}, {%4,%5,%6,%7}, {%8,%9}, {%0,%1,%2,%3};"
        : "+f"(c[0]), "+f"(c[1]), "+f"(c[2]), "+f"(c[3])
        : "r"(a[0]), "r"(a[1]), "r"(a[2]), "r"(a[3]), "r"(b[0]), "r"(b[1]));
}

static __device__ __forceinline__ void ldsm_x4(uint32_t* r, uint32_t addr) {
    asm volatile("ldmatrix.sync.aligned.m8n8.x4.shared.b16 {%0,%1,%2,%3}, [%4];"
                 : "=r"(r[0]), "=r"(r[1]), "=r"(r[2]), "=r"(r[3]) : "r"(addr));
}

// tf32 round-to-nearest via +half-ulp; tensor core truncates low 13 bits.
static __device__ __forceinline__ uint32_t round_tf32(uint32_t v) {
    return v + 0x1000u;
}

static __device__ __forceinline__ void cpasync16(uint32_t dst, const void* src) {
    asm volatile("cp.async.cg.shared.global [%0], [%1], 16;"
                 :: "r"(dst), "l"(src) : "memory");
}
#define CP_COMMIT() asm volatile("cp.async.commit_group;" ::: "memory")
#define CP_WAIT2()  asm volatile("cp.async.wait_group 2;" ::: "memory")

// swizzled byte offset of 16B granule g (0..3) in 64B row r
static __device__ __forceinline__ uint32_t sw_off(int r, int g) {
    return (uint32_t)((r >> 1) * 128 + (((g + (r & 1) * 4) ^ ((r >> 1) & 7)) << 4));
}

__global__ void __launch_bounds__(256, 4)
tdconv_tf32q4_kernel(const float* __restrict__ x,
                     const float* __restrict__ w,
                     const float* __restrict__ bias,
                     float* __restrict__ y)
{
    extern __shared__ char smem[];
    const uint32_t sbase = smem_u32(smem);

    const int p    = blockIdx.x;
    const int tid  = threadIdx.x;
    const int wid  = tid >> 5;
    const int lane = tid & 31;

    const int mrow = (wid >> 1) * 32;   // cout base (0,32,64,96)
    const int ncol = (wid & 1) * 32;    // batch base (0,32)

    // contributing blocks: k = par + 2j, l = m - j, j in [j0, j1]
    const int par = p & 1;
    const int m   = (p - par) >> 1;
    int j0 = m - (LIN - 1); if (j0 < 0) j0 = 0;
    int j1 = m < 3 ? m : 3;
    const int nblk    = j1 - j0 + 1;
    const int nchunks = 8 * nblk;       // K=16 slices

    // producer decomposition: thread -> (row cr 0..63, granule cg 0..3)
    const int cr = tid >> 2;
    const int cg = tid & 3;
    const uint32_t d0 = sw_off(cr, cg);     // A rows 0-63 & B rows 0-63
    // A rows 64-127: sw_off(cr+64, cg) = d0 + 4096 (64 rows = 32 lines)

    // issue cp.async for chunk c (block c>>3, K-slice c&7) into buf[c&3]
    auto issue_chunk = [&](int c) {
        if (c < nchunks) {
            const int j = j0 + (c >> 3);
            const int l = m - j;
            const int k = par + 2 * j;
            const int kh = (c & 7) * 16;
            const float* __restrict__ wp =
                w + (size_t)(k * LIN + l) * (COUT * CIN)
                  + (size_t)cr * CIN + kh + cg * 4;
            const float* __restrict__ xp =
                x + ((size_t)cr * LIN + l) * CIN + kh + cg * 4;
            const uint32_t buf = sbase + (uint32_t)(c & 3) * BUF_BYTES;
            cpasync16(buf + A_OFF + d0,        wp);
            cpasync16(buf + A_OFF + d0 + 4096, wp + 64 * CIN);
            cpasync16(buf + B_OFF + d0,        xp);
        }
        CP_COMMIT();   // uniform group counting
    };

    // consumer (ldmatrix) lane constants
    const int q   = (lane & 7) + ((lane >> 3) & 1) * 8;   // A row-in-tile 0..15
    const int hi  = lane >> 4;                            // A k-granule half
    const uint32_t a_line = (uint32_t)(mrow / 2 + (q >> 1)) * 128;
    const int a_add = (q & 1) * 4, a_s = q >> 1;

    const int qb  = (lane & 7) + (lane >> 4) * 8;         // B row-in-tile 0..15
    const int hb  = (lane >> 3) & 1;                      // B k-granule half
    const uint32_t b_line = (uint32_t)(ncol / 2 + (qb >> 1)) * 128;
    const int b_add = (qb & 1) * 4, b_s = qb >> 1;

    // accumulators init with bias (same across batch cols)
    const int g = lane >> 2;
    float acc[2][4][4];
    #pragma unroll
    for (int mi = 0; mi < 2; mi++) {
        const float b_g  = bias[p * COUT + mrow + mi * 16 + g];
        const float b_g8 = bias[p * COUT + mrow + mi * 16 + g + 8];
        #pragma unroll
        for (int ni = 0; ni < 4; ni++) {
            acc[mi][ni][0] = b_g;  acc[mi][ni][1] = b_g;
            acc[mi][ni][2] = b_g8; acc[mi][ni][3] = b_g8;
        }
    }

    // prologue: 3 chunks in flight
    issue_chunk(0);
    issue_chunk(1);
    issue_chunk(2);

    for (int c = 0; c < nchunks; c++) {
        CP_WAIT2();               // group c retired (c+1, c+2 may be pending)
        __syncthreads();          // chunk c visible; buf[(c+3)&3] free to refill

        issue_chunk(c + 3);       // refill BEFORE compute (lead 2-3 chunks)

        const uint32_t buf = sbase + (uint32_t)(c & 3) * BUF_BYTES;
        const uint32_t ab = buf + A_OFF + a_line;
        const uint32_t bb = buf + B_OFF + b_line;

        #pragma unroll
        for (int ks = 0; ks < 2; ks++) {           // 2 k8-steps over K=16
            const uint32_t xa = (uint32_t)(((2 * ks + hi + a_add) ^ a_s) << 4);
            const uint32_t xb = (uint32_t)(((2 * ks + hb + b_add) ^ b_s) << 4);
            uint32_t a[2][4], b[2][4];
            #pragma unroll
            for (int mi = 0; mi < 2; mi++)
                ldsm_x4(a[mi], ab + (uint32_t)mi * 1024 + xa);
            #pragma unroll
            for (int pr = 0; pr < 2; pr++)
                ldsm_x4(b[pr], bb + (uint32_t)pr * 1024 + xb);

            #pragma unroll
            for (int mi = 0; mi < 2; mi++)
                #pragma unroll
                for (int qq = 0; qq < 4; qq++) a[mi][qq] = round_tf32(a[mi][qq]);
            #pragma unroll
            for (int pr = 0; pr < 2; pr++)
                #pragma unroll
                for (int qq = 0; qq < 4; qq++) b[pr][qq] = round_tf32(b[pr][qq]);

            #pragma unroll
            for (int mi = 0; mi < 2; mi++)
                #pragma unroll
                for (int ni = 0; ni < 4; ni++)
                    mma_tf32(acc[mi][ni], a[mi], &b[ni >> 1][(ni & 1) * 2]);
        }
    }

    // ---- epilogue: D[o,b] -> y[b,p,o] ----
    const int t = lane & 3;
    #pragma unroll
    for (int mi = 0; mi < 2; mi++) {
        const int o0 = mrow + mi * 16 + g;
        const int o8 = o0 + 8;
        #pragma unroll
        for (int ni = 0; ni < 4; ni++) {
            const int b0 = ncol + ni * 8 + 2 * t;
            float* y0 = y + ((size_t)b0 * OUTP + p) * COUT;
            float* y1 = y0 + (size_t)OUTP * COUT;
            y0[o0] = acc[mi][ni][0];
            y1[o0] = acc[mi][ni][1];
            y0[o8] = acc[mi][ni][2];
            y1[o8] = acc[mi][ni][3];
        }
    }
}

extern "C" void kernel_launch(void* const* d_in, const int* in_sizes, int n_in,
                              void* d_out, int out_size)
{
    const float* x    = (const float*)d_in[0];  // (64,512,128)
    const float* w    = (const float*)d_in[1];  // (8,512,128,128)
    const float* bias = (const float*)d_in[2];  // (1030,128)
    float* y = (float*)d_out;                   // (64,1030,128)

    tdconv_tf32q4_kernel<<<OUTP, 256, SMEM_TOTAL>>>(x, w, bias, y);
}